// round 5
// baseline (speedup 1.0000x reference)
#include <cuda_runtime.h>

#define N_NODES 2048
#define N_EDGES 16384
#define B_DIM 8
#define C_DIM 64
#define T_DIM 12
#define BT 96                 // B*T
#define OUT_DIM 64

// ---------------- scratch (static __device__, no allocation) ----------------
__device__ float g_h2[N_NODES * BT * C_DIM];     // h * log2(e), [n][bt][c]
__device__ float g_feats[BT * N_NODES * C_DIM];  // h + agg,     [bt][n][c]
__device__ int   g_cnt[N_NODES];
__device__ int   g_epack[N_NODES * 64];          // (eid<<11)|src per dst slot

// ---------------- packed f32x2 helpers ----------------
union F2U { float2 f; unsigned long long u; };
__device__ __forceinline__ float2 f2add(float2 a, float2 b) {
    F2U A, B2, D; A.f = a; B2.f = b;
    asm("add.rn.f32x2 %0, %1, %2;" : "=l"(D.u) : "l"(A.u), "l"(B2.u));
    return D.f;
}
__device__ __forceinline__ float2 f2fma(float2 a, float2 b, float2 c) {
    F2U A, B2, C2, D; A.f = a; B2.f = b; C2.f = c;
    asm("fma.rn.f32x2 %0, %1, %2, %3;" : "=l"(D.u) : "l"(A.u), "l"(B2.u), "l"(C2.u));
    return D.f;
}
__device__ __forceinline__ float4 f4add(float4 a, float4 b) {
    float2 lo = f2add(make_float2(a.x, a.y), make_float2(b.x, b.y));
    float2 hi = f2add(make_float2(a.z, a.w), make_float2(b.z, b.w));
    return make_float4(lo.x, lo.y, hi.x, hi.y);
}
__device__ __forceinline__ float ex2f(float x) {
    float r; asm("ex2.approx.f32 %0, %1;" : "=f"(r) : "f"(x)); return r;
}
__device__ __forceinline__ float rcpf(float x) {
    float r; asm("rcp.approx.f32 %0, %1;" : "=f"(r) : "f"(x)); return r;
}

// ---------------- stage A: transpose [B,C,T,N] -> [N,BT,C] (*log2e),
//                  plus (extra z-slice) counter zeroing ----------------------
__global__ void k_transpose(const float* __restrict__ nf) {
    if (blockIdx.z == BT) {
        if (blockIdx.x == 0 && blockIdx.y == 0) {
            int t = threadIdx.y * 32 + threadIdx.x;
            for (int i = t; i < N_NODES; i += 256) g_cnt[i] = 0;
        }
        return;
    }
    __shared__ float tile[32][33];
    const float LOG2E = 1.4426950408889634f;
    int bt = blockIdx.z;
    int b = bt / T_DIM, t = bt - b * T_DIM;
    int c0 = blockIdx.y << 5, n0 = blockIdx.x << 5;
    int tx = threadIdx.x, ty = threadIdx.y;
#pragma unroll
    for (int i = 0; i < 4; i++) {
        int c = c0 + ty + i * 8;
        tile[ty + i * 8][tx] =
            nf[(((b * C_DIM + c) * T_DIM + t) * N_NODES) + n0 + tx] * LOG2E;
    }
    __syncthreads();
#pragma unroll
    for (int i = 0; i < 4; i++) {
        int n = n0 + ty + i * 8;
        g_h2[((n * BT + bt) << 6) + c0 + tx] = tile[tx][ty + i * 8];
    }
}

// ---------------- stage 0b: bucket-place edges per destination -------------
__global__ void k_build(const int* __restrict__ src, const int* __restrict__ dst) {
    int e = blockIdx.x * blockDim.x + threadIdx.x;
    int d = dst[e];
    int p = atomicAdd(&g_cnt[d], 1);
    g_epack[(d << 6) + p] = (e << 11) | src[e];
}

// ---------------- stage B: message + softmax + agg + residual ---------------
// grid (N_NODES, 3), block 256: cq = tid&15 (c-quad), grp = tid>>4 (16 groups),
// each thread owns 2 bt slots. Edge features staged in smem once per block.
// No max-pass needed: r = relu(.)*log2e in [0,~16], 2^r cannot overflow.
#define BT_PER_BLK 32
__global__ __launch_bounds__(256, 4) void k_msg(const float* __restrict__ ef) {
    __shared__ __align__(16) float s_ev[64 * 64];
    __shared__ int s_ep[64];
    __shared__ int s_cnt;
    int n = blockIdx.x;
    int tid = threadIdx.x;
    if (tid == 0) s_cnt = g_cnt[n];
    if (tid < 64) s_ep[tid] = g_epack[(n << 6) + tid];
    __syncthreads();
    int cnt = s_cnt;
    const float LOG2E = 1.4426950408889634f;
    for (int i = tid; i < (cnt << 6); i += 256) {
        int eid = s_ep[i >> 6] >> 11;
        s_ev[i] = ef[(eid << 6) + (i & 63)] * LOG2E;   // coalesced stage
    }
    __syncthreads();

    int cq = tid & 15;     // c-quad: c = 4*cq .. 4*cq+3
    int grp = tid >> 4;    // 0..15
    int bt0 = blockIdx.y * BT_PER_BLK + grp * 2;

    float4 den0 = make_float4(0, 0, 0, 0), den1 = den0;
    float4 num0 = den0, num1 = den0;

    const float4* evp = (const float4*)s_ev;   // [edge][16 quads]

#define PROC(Hq, Eq, DEN, NUM)                                            \
    {                                                                     \
        float4 v = f4add(Hq, Eq);                                         \
        float4 r = make_float4(fmaxf(v.x, 0.f), fmaxf(v.y, 0.f),          \
                               fmaxf(v.z, 0.f), fmaxf(v.w, 0.f));         \
        float4 p = make_float4(ex2f(r.x), ex2f(r.y), ex2f(r.z), ex2f(r.w)); \
        DEN = f4add(DEN, p);                                              \
        float2 nlo = f2fma(make_float2(r.x, r.y), make_float2(p.x, p.y),  \
                           make_float2(NUM.x, NUM.y));                    \
        float2 nhi = f2fma(make_float2(r.z, r.w), make_float2(p.z, p.w),  \
                           make_float2(NUM.z, NUM.w));                    \
        NUM = make_float4(nlo.x, nlo.y, nhi.x, nhi.y);                    \
    }

    int k = 0;
    for (; k + 2 <= cnt; k += 2) {
        int s0 = s_ep[k] & 2047;
        int s1 = s_ep[k + 1] & 2047;
        const float4* h0 = (const float4*)(g_h2 + (s0 * BT + bt0) * 64) + cq;
        const float4* h1 = (const float4*)(g_h2 + (s1 * BT + bt0) * 64) + cq;
        float4 a0 = h0[0], a1 = h0[16];     // bt0, bt0+1 of edge0
        float4 b0 = h1[0], b1 = h1[16];     // bt0, bt0+1 of edge1
        float4 e0 = evp[(k << 4) + cq];
        float4 e1 = evp[((k + 1) << 4) + cq];
        PROC(a0, e0, den0, num0);
        PROC(a1, e0, den1, num1);
        PROC(b0, e1, den0, num0);
        PROC(b1, e1, den1, num1);
    }
    if (k < cnt) {
        int s0 = s_ep[k] & 2047;
        const float4* h0 = (const float4*)(g_h2 + (s0 * BT + bt0) * 64) + cq;
        float4 a0 = h0[0], a1 = h0[16];
        float4 e0 = evp[(k << 4) + cq];
        PROC(a0, e0, den0, num0);
        PROC(a1, e0, den1, num1);
    }
#undef PROC

    const float LN2 = 0.6931471805599453f;
    const float EPS = 1e-7f;
    const float4* hq = (const float4*)(g_h2 + (n * BT + bt0) * 64) + cq;
    bool has = (cnt > 0);
#pragma unroll
    for (int j = 0; j < 2; j++) {
        float4 den = j ? den1 : den0;
        float4 num = j ? num1 : num0;
        float4 h = hq[j * 16];
        float4 agg = make_float4(0, 0, 0, 0);
        if (has) {
            agg.x = fmaf(num.x * rcpf(den.x), LN2, EPS);
            agg.y = fmaf(num.y * rcpf(den.y), LN2, EPS);
            agg.z = fmaf(num.z * rcpf(den.z), LN2, EPS);
            agg.w = fmaf(num.w * rcpf(den.w), LN2, EPS);
        }
        float4 o;
        o.x = fmaf(h.x, LN2, agg.x);
        o.y = fmaf(h.y, LN2, agg.y);
        o.z = fmaf(h.z, LN2, agg.z);
        o.w = fmaf(h.w, LN2, agg.w);
        // feats layout [bt][n][c]
        float4* fq = (float4*)(g_feats + (((bt0 + j) * N_NODES + n) << 6)) + cq;
        *fq = o;
    }
}

// ---------------- stage C: register-tiled GEMM, out [B,O,T,N] ---------------
// grid (16 n-blocks, 96 bt), block 128. Thread tile: 8n x 8o.
// tx = tid&15 (n-octet), ty = tid>>4 (o-octet). smem: sA 32KB + sW 16KB = 48KB.
__global__ __launch_bounds__(128) void k_gemm(const float* __restrict__ W,
                                              const float* __restrict__ bias,
                                              float* __restrict__ out) {
    __shared__ float sA[64][128];                 // [c][n] 32KB
    __shared__ __align__(16) float sW[64 * 64];   // [c][o] 16KB
    int tid = threadIdx.x;
    int bt = blockIdx.y;
    int n0 = blockIdx.x << 7;

    // W: coalesced copy ([c][o], o contiguous); 1024 float4 over 128 threads
    {
        const float4* Wv = (const float4*)W;
        float4* sWv = (float4*)sW;
#pragma unroll
        for (int i = 0; i < 8; i++) sWv[tid + i * 128] = Wv[tid + i * 128];
    }
    // feats tile: row r = tid (128 rows), transpose into sA[c][r]
    {
        const float4* fp = (const float4*)(g_feats + ((bt * N_NODES + n0 + tid) << 6));
#pragma unroll
        for (int q = 0; q < 16; q++) {
            float4 v = fp[q];
            int c = q << 2;
            sA[c][tid] = v.x; sA[c + 1][tid] = v.y;
            sA[c + 2][tid] = v.z; sA[c + 3][tid] = v.w;
        }
    }
    __syncthreads();

    int tx = tid & 15;   // n-octet: n = n0 + tx*8 .. +7
    int ty = tid >> 4;   // o-octet: o = ty*8 .. +7

    float2 acc[8][4];
#pragma unroll
    for (int i = 0; i < 8; i++)
#pragma unroll
        for (int p = 0; p < 4; p++) acc[i][p] = make_float2(0.f, 0.f);

    const float4* sWv4 = (const float4*)sW;
#pragma unroll 4
    for (int c = 0; c < 64; c++) {
        float4 a0 = *(const float4*)&sA[c][tx << 3];
        float4 a1 = *(const float4*)&sA[c][(tx << 3) + 4];
        float4 w0 = sWv4[(c << 4) + (ty << 1)];       // uniform within half-warp
        float4 w1 = sWv4[(c << 4) + (ty << 1) + 1];
        float2 wp[4] = {{w0.x, w0.y}, {w0.z, w0.w}, {w1.x, w1.y}, {w1.z, w1.w}};
        float av[8] = {a0.x, a0.y, a0.z, a0.w, a1.x, a1.y, a1.z, a1.w};
#pragma unroll
        for (int i = 0; i < 8; i++) {
            float2 ad = make_float2(av[i], av[i]);
#pragma unroll
            for (int p = 0; p < 4; p++) acc[i][p] = f2fma(ad, wp[p], acc[i][p]);
        }
    }

    // epilogue: +bias (L1-resident uniform LDG), STG.128 over n per output o
    int b = bt / T_DIM, t = bt - b * T_DIM;
    float* obase = out + ((b * OUT_DIM) * T_DIM + t) * N_NODES + n0 + (tx << 3);
#pragma unroll
    for (int p = 0; p < 4; p++) {
        int oe = (ty << 3) + (p << 1);
        float b0 = __ldg(bias + oe), b1 = __ldg(bias + oe + 1);
        float4 v0a, v0b, v1a, v1b;
        v0a.x = acc[0][p].x + b0; v0a.y = acc[1][p].x + b0;
        v0a.z = acc[2][p].x + b0; v0a.w = acc[3][p].x + b0;
        v0b.x = acc[4][p].x + b0; v0b.y = acc[5][p].x + b0;
        v0b.z = acc[6][p].x + b0; v0b.w = acc[7][p].x + b0;
        v1a.x = acc[0][p].y + b1; v1a.y = acc[1][p].y + b1;
        v1a.z = acc[2][p].y + b1; v1a.w = acc[3][p].y + b1;
        v1b.x = acc[4][p].y + b1; v1b.y = acc[5][p].y + b1;
        v1b.z = acc[6][p].y + b1; v1b.w = acc[7][p].y + b1;
        long long so = (long long)oe * (T_DIM * N_NODES);
        long long s1 = (long long)(oe + 1) * (T_DIM * N_NODES);
        *(float4*)(obase + so) = v0a;
        *(float4*)(obase + so + 4) = v0b;
        *(float4*)(obase + s1) = v1a;
        *(float4*)(obase + s1 + 4) = v1b;
    }
}

// ---------------- launch ----------------
extern "C" void kernel_launch(void* const* d_in, const int* in_sizes, int n_in,
                              void* d_out, int out_size) {
    const float* nf   = (const float*)d_in[0];  // node_feats [B,C,T,N]
    const float* ef   = (const float*)d_in[1];  // edge_feat  [E,1,1,C]
    const int*   src  = (const int*)d_in[2];
    const int*   dst  = (const int*)d_in[3];
    const float* W    = (const float*)d_in[4];
    const float* bvec = (const float*)d_in[5];
    float* out = (float*)d_out;

    k_transpose<<<dim3(N_NODES / 32, C_DIM / 32, BT + 1), dim3(32, 8)>>>(nf);
    k_build<<<N_EDGES / 256, 256>>>(src, dst);
    k_msg<<<dim3(N_NODES, 3), 256>>>(ef);
    k_gemm<<<dim3(N_NODES / 128, BT), 128>>>(W, bvec, out);
}

// round 6
// speedup vs baseline: 1.0041x; 1.0041x over previous
#include <cuda_runtime.h>

#define N_NODES 2048
#define N_EDGES 16384
#define B_DIM 8
#define C_DIM 64
#define T_DIM 12
#define BT 96                 // B*T
#define OUT_DIM 64

// ---------------- scratch (static __device__, no allocation) ----------------
__device__ float g_h2[N_NODES * BT * C_DIM];     // h * log2(e), [n][bt][c]
__device__ float g_feats[BT * N_NODES * C_DIM];  // h + agg,     [bt][n][c]
__device__ int   g_cnt[N_NODES];
__device__ int   g_epack[N_NODES * 64];          // (eid<<11)|src per dst slot

// ---------------- packed f32x2 helpers ----------------
union F2U { float2 f; unsigned long long u; };
__device__ __forceinline__ float2 f2add(float2 a, float2 b) {
    F2U A, B2, D; A.f = a; B2.f = b;
    asm("add.rn.f32x2 %0, %1, %2;" : "=l"(D.u) : "l"(A.u), "l"(B2.u));
    return D.f;
}
__device__ __forceinline__ float2 f2fma(float2 a, float2 b, float2 c) {
    F2U A, B2, C2, D; A.f = a; B2.f = b; C2.f = c;
    asm("fma.rn.f32x2 %0, %1, %2, %3;" : "=l"(D.u) : "l"(A.u), "l"(B2.u), "l"(C2.u));
    return D.f;
}
__device__ __forceinline__ float4 f4add(float4 a, float4 b) {
    float2 lo = f2add(make_float2(a.x, a.y), make_float2(b.x, b.y));
    float2 hi = f2add(make_float2(a.z, a.w), make_float2(b.z, b.w));
    return make_float4(lo.x, lo.y, hi.x, hi.y);
}
__device__ __forceinline__ float ex2f(float x) {
    float r; asm("ex2.approx.f32 %0, %1;" : "=f"(r) : "f"(x)); return r;
}
__device__ __forceinline__ float rcpf(float x) {
    float r; asm("rcp.approx.f32 %0, %1;" : "=f"(r) : "f"(x)); return r;
}

// ---------------- stage A: transpose [B,C,T,N] -> [N,BT,C] (*log2e),
//                  plus (extra z-slice) counter zeroing ----------------------
__global__ void k_transpose(const float* __restrict__ nf) {
    if (blockIdx.z == BT) {
        if (blockIdx.x == 0 && blockIdx.y == 0) {
            int t = threadIdx.y * 32 + threadIdx.x;
            for (int i = t; i < N_NODES; i += 256) g_cnt[i] = 0;
        }
        return;
    }
    __shared__ float tile[32][33];
    const float LOG2E = 1.4426950408889634f;
    int bt = blockIdx.z;
    int b = bt / T_DIM, t = bt - b * T_DIM;
    int c0 = blockIdx.y << 5, n0 = blockIdx.x << 5;
    int tx = threadIdx.x, ty = threadIdx.y;
#pragma unroll
    for (int i = 0; i < 4; i++) {
        int c = c0 + ty + i * 8;
        tile[ty + i * 8][tx] =
            nf[(((b * C_DIM + c) * T_DIM + t) * N_NODES) + n0 + tx] * LOG2E;
    }
    __syncthreads();
#pragma unroll
    for (int i = 0; i < 4; i++) {
        int n = n0 + ty + i * 8;
        g_h2[((n * BT + bt) << 6) + c0 + tx] = tile[tx][ty + i * 8];
    }
}

// ---------------- stage 0b: bucket-place edges per destination -------------
__global__ void k_build(const int* __restrict__ src, const int* __restrict__ dst) {
    int e = blockIdx.x * blockDim.x + threadIdx.x;
    int d = dst[e];
    int p = atomicAdd(&g_cnt[d], 1);
    g_epack[(d << 6) + p] = (e << 11) | src[e];
}

// ---------------- stage B: message + softmax + agg + residual ---------------
// grid (N_NODES, 3), block 256: cq = tid&15 (c-quad), grp = tid>>4 (16 groups),
// each thread owns 2 bt slots. Edge features staged in smem once per block.
// No max-pass needed: r = relu(.)*log2e in [0,~16], 2^r cannot overflow.
#define BT_PER_BLK 32
__global__ __launch_bounds__(256, 4) void k_msg(const float* __restrict__ ef) {
    __shared__ __align__(16) float s_ev[64 * 64];
    __shared__ int s_ep[64];
    __shared__ int s_cnt;
    int n = blockIdx.x;
    int tid = threadIdx.x;
    if (tid == 0) s_cnt = g_cnt[n];
    if (tid < 64) s_ep[tid] = g_epack[(n << 6) + tid];
    __syncthreads();
    int cnt = s_cnt;
    const float LOG2E = 1.4426950408889634f;
    for (int i = tid; i < (cnt << 6); i += 256) {
        int eid = s_ep[i >> 6] >> 11;
        s_ev[i] = ef[(eid << 6) + (i & 63)] * LOG2E;   // coalesced stage
    }
    __syncthreads();

    int cq = tid & 15;     // c-quad: c = 4*cq .. 4*cq+3
    int grp = tid >> 4;    // 0..15
    int bt0 = blockIdx.y * BT_PER_BLK + grp * 2;

    float4 den0 = make_float4(0, 0, 0, 0), den1 = den0;
    float4 num0 = den0, num1 = den0;

    const float4* evp = (const float4*)s_ev;   // [edge][16 quads]

#define PROC(Hq, Eq, DEN, NUM)                                            \
    {                                                                     \
        float4 v = f4add(Hq, Eq);                                         \
        float4 r = make_float4(fmaxf(v.x, 0.f), fmaxf(v.y, 0.f),          \
                               fmaxf(v.z, 0.f), fmaxf(v.w, 0.f));         \
        float4 p = make_float4(ex2f(r.x), ex2f(r.y), ex2f(r.z), ex2f(r.w)); \
        DEN = f4add(DEN, p);                                              \
        float2 nlo = f2fma(make_float2(r.x, r.y), make_float2(p.x, p.y),  \
                           make_float2(NUM.x, NUM.y));                    \
        float2 nhi = f2fma(make_float2(r.z, r.w), make_float2(p.z, p.w),  \
                           make_float2(NUM.z, NUM.w));                    \
        NUM = make_float4(nlo.x, nlo.y, nhi.x, nhi.y);                    \
    }

    int k = 0;
    for (; k + 2 <= cnt; k += 2) {
        int s0 = s_ep[k] & 2047;
        int s1 = s_ep[k + 1] & 2047;
        const float4* h0 = (const float4*)(g_h2 + (s0 * BT + bt0) * 64) + cq;
        const float4* h1 = (const float4*)(g_h2 + (s1 * BT + bt0) * 64) + cq;
        float4 a0 = h0[0], a1 = h0[16];     // bt0, bt0+1 of edge0
        float4 b0 = h1[0], b1 = h1[16];     // bt0, bt0+1 of edge1
        float4 e0 = evp[(k << 4) + cq];
        float4 e1 = evp[((k + 1) << 4) + cq];
        PROC(a0, e0, den0, num0);
        PROC(a1, e0, den1, num1);
        PROC(b0, e1, den0, num0);
        PROC(b1, e1, den1, num1);
    }
    if (k < cnt) {
        int s0 = s_ep[k] & 2047;
        const float4* h0 = (const float4*)(g_h2 + (s0 * BT + bt0) * 64) + cq;
        float4 a0 = h0[0], a1 = h0[16];
        float4 e0 = evp[(k << 4) + cq];
        PROC(a0, e0, den0, num0);
        PROC(a1, e0, den1, num1);
    }
#undef PROC

    const float LN2 = 0.6931471805599453f;
    const float EPS = 1e-7f;
    const float4* hq = (const float4*)(g_h2 + (n * BT + bt0) * 64) + cq;
    bool has = (cnt > 0);
#pragma unroll
    for (int j = 0; j < 2; j++) {
        float4 den = j ? den1 : den0;
        float4 num = j ? num1 : num0;
        float4 h = hq[j * 16];
        float4 agg = make_float4(0, 0, 0, 0);
        if (has) {
            agg.x = fmaf(num.x * rcpf(den.x), LN2, EPS);
            agg.y = fmaf(num.y * rcpf(den.y), LN2, EPS);
            agg.z = fmaf(num.z * rcpf(den.z), LN2, EPS);
            agg.w = fmaf(num.w * rcpf(den.w), LN2, EPS);
        }
        float4 o;
        o.x = fmaf(h.x, LN2, agg.x);
        o.y = fmaf(h.y, LN2, agg.y);
        o.z = fmaf(h.z, LN2, agg.z);
        o.w = fmaf(h.w, LN2, agg.w);
        // feats layout [bt][n][c]
        float4* fq = (float4*)(g_feats + (((bt0 + j) * N_NODES + n) << 6)) + cq;
        *fq = o;
    }
}

// ---------------- stage C: register-tiled GEMM, out [B,O,T,N] ---------------
// grid (16 n-blocks, 96 bt), block 128. Thread tile: 8n x 8o.
// Explicit register double-buffering: loads for c+1 issued before FMAs of c,
// so each warp self-covers the ~29cyc LDS latency with 64cyc of FMA work.
__global__ __launch_bounds__(128) void k_gemm(const float* __restrict__ W,
                                              const float* __restrict__ bias,
                                              float* __restrict__ out) {
    __shared__ float sA[64][128];                 // [c][n] 32KB
    __shared__ __align__(16) float sW[64 * 64];   // [c][o] 16KB
    int tid = threadIdx.x;
    int bt = blockIdx.y;
    int n0 = blockIdx.x << 7;

    // W: coalesced copy ([c][o], o contiguous); 1024 float4 over 128 threads
    {
        const float4* Wv = (const float4*)W;
        float4* sWv = (float4*)sW;
#pragma unroll
        for (int i = 0; i < 8; i++) sWv[tid + i * 128] = Wv[tid + i * 128];
    }
    // feats tile: row r = tid (128 rows), transpose into sA[c][r]
    {
        const float4* fp = (const float4*)(g_feats + ((bt * N_NODES + n0 + tid) << 6));
#pragma unroll
        for (int q = 0; q < 16; q++) {
            float4 v = fp[q];
            int c = q << 2;
            sA[c][tid] = v.x; sA[c + 1][tid] = v.y;
            sA[c + 2][tid] = v.z; sA[c + 3][tid] = v.w;
        }
    }
    __syncthreads();

    int tx = tid & 15;   // n-octet: n = n0 + tx*8 .. +7
    int ty = tid >> 4;   // o-octet: o = ty*8 .. +7

    float2 acc[8][4];
#pragma unroll
    for (int i = 0; i < 8; i++)
#pragma unroll
        for (int p = 0; p < 4; p++) acc[i][p] = make_float2(0.f, 0.f);

    const float4* sWv4 = (const float4*)sW;
    // pipeline prologue: load c=0 operands
    float4 a0 = *(const float4*)&sA[0][tx << 3];
    float4 a1 = *(const float4*)&sA[0][(tx << 3) + 4];
    float4 w0 = sWv4[(ty << 1)];
    float4 w1 = sWv4[(ty << 1) + 1];

#pragma unroll 4
    for (int c = 0; c < 64; c++) {
        // prefetch c+1 ((c+1)&63 wraps harmlessly on last iter)
        int cn = (c + 1) & 63;
        float4 na0 = *(const float4*)&sA[cn][tx << 3];
        float4 na1 = *(const float4*)&sA[cn][(tx << 3) + 4];
        float4 nw0 = sWv4[(cn << 4) + (ty << 1)];
        float4 nw1 = sWv4[(cn << 4) + (ty << 1) + 1];

        float2 wp[4] = {{w0.x, w0.y}, {w0.z, w0.w}, {w1.x, w1.y}, {w1.z, w1.w}};
        float av[8] = {a0.x, a0.y, a0.z, a0.w, a1.x, a1.y, a1.z, a1.w};
#pragma unroll
        for (int i = 0; i < 8; i++) {
            float2 ad = make_float2(av[i], av[i]);
#pragma unroll
            for (int p = 0; p < 4; p++) acc[i][p] = f2fma(ad, wp[p], acc[i][p]);
        }
        a0 = na0; a1 = na1; w0 = nw0; w1 = nw1;
    }

    // epilogue: +bias (L1-resident uniform LDG), STG.128 over n per output o
    int b = bt / T_DIM, t = bt - b * T_DIM;
    float* obase = out + ((b * OUT_DIM) * T_DIM + t) * N_NODES + n0 + (tx << 3);
#pragma unroll
    for (int p = 0; p < 4; p++) {
        int oe = (ty << 3) + (p << 1);
        float b0 = __ldg(bias + oe), b1 = __ldg(bias + oe + 1);
        float4 v0a, v0b, v1a, v1b;
        v0a.x = acc[0][p].x + b0; v0a.y = acc[1][p].x + b0;
        v0a.z = acc[2][p].x + b0; v0a.w = acc[3][p].x + b0;
        v0b.x = acc[4][p].x + b0; v0b.y = acc[5][p].x + b0;
        v0b.z = acc[6][p].x + b0; v0b.w = acc[7][p].x + b0;
        v1a.x = acc[0][p].y + b1; v1a.y = acc[1][p].y + b1;
        v1a.z = acc[2][p].y + b1; v1a.w = acc[3][p].y + b1;
        v1b.x = acc[4][p].y + b1; v1b.y = acc[5][p].y + b1;
        v1b.z = acc[6][p].y + b1; v1b.w = acc[7][p].y + b1;
        long long so = (long long)oe * (T_DIM * N_NODES);
        long long s1 = (long long)(oe + 1) * (T_DIM * N_NODES);
        *(float4*)(obase + so) = v0a;
        *(float4*)(obase + so + 4) = v0b;
        *(float4*)(obase + s1) = v1a;
        *(float4*)(obase + s1 + 4) = v1b;
    }
}

// ---------------- launch ----------------
extern "C" void kernel_launch(void* const* d_in, const int* in_sizes, int n_in,
                              void* d_out, int out_size) {
    const float* nf   = (const float*)d_in[0];  // node_feats [B,C,T,N]
    const float* ef   = (const float*)d_in[1];  // edge_feat  [E,1,1,C]
    const int*   src  = (const int*)d_in[2];
    const int*   dst  = (const int*)d_in[3];
    const float* W    = (const float*)d_in[4];
    const float* bvec = (const float*)d_in[5];
    float* out = (float*)d_out;

    k_transpose<<<dim3(N_NODES / 32, C_DIM / 32, BT + 1), dim3(32, 8)>>>(nf);
    k_build<<<N_EDGES / 256, 256>>>(src, dst);
    k_msg<<<dim3(N_NODES, 3), 256>>>(ef);
    k_gemm<<<dim3(N_NODES / 128, BT), 128>>>(W, bvec, out);
}

// round 7
// speedup vs baseline: 1.0714x; 1.0669x over previous
#include <cuda_runtime.h>

#define N_NODES 2048
#define N_EDGES 16384
#define B_DIM 8
#define C_DIM 64
#define T_DIM 12
#define BT 96                 // B*T
#define OUT_DIM 64

// ---------------- scratch (static __device__, no allocation) ----------------
__device__ float g_h2[N_NODES * BT * C_DIM];     // h * log2(e), [n][bt][c]
__device__ float g_feats[BT * N_NODES * C_DIM];  // h + agg,     [bt][n][c]
__device__ int   g_cnt[N_NODES];
__device__ int   g_epack[N_NODES * 64];          // (eid<<11)|src per dst slot

// ---------------- packed f32x2 helpers ----------------
union F2U { float2 f; unsigned long long u; };
__device__ __forceinline__ float2 f2add(float2 a, float2 b) {
    F2U A, B2, D; A.f = a; B2.f = b;
    asm("add.rn.f32x2 %0, %1, %2;" : "=l"(D.u) : "l"(A.u), "l"(B2.u));
    return D.f;
}
__device__ __forceinline__ float2 f2fma(float2 a, float2 b, float2 c) {
    F2U A, B2, C2, D; A.f = a; B2.f = b; C2.f = c;
    asm("fma.rn.f32x2 %0, %1, %2, %3;" : "=l"(D.u) : "l"(A.u), "l"(B2.u), "l"(C2.u));
    return D.f;
}
__device__ __forceinline__ float4 f4add(float4 a, float4 b) {
    float2 lo = f2add(make_float2(a.x, a.y), make_float2(b.x, b.y));
    float2 hi = f2add(make_float2(a.z, a.w), make_float2(b.z, b.w));
    return make_float4(lo.x, lo.y, hi.x, hi.y);
}
__device__ __forceinline__ float ex2f(float x) {
    float r; asm("ex2.approx.f32 %0, %1;" : "=f"(r) : "f"(x)); return r;
}
__device__ __forceinline__ float rcpf(float x) {
    float r; asm("rcp.approx.f32 %0, %1;" : "=f"(r) : "f"(x)); return r;
}

// ---------------- stage A: transpose [B,C,T,N] -> [N,BT,C] (*log2e),
//                  plus (extra z-slice) counter zeroing ----------------------
__global__ void k_transpose(const float* __restrict__ nf) {
    if (blockIdx.z == BT) {
        if (blockIdx.x == 0 && blockIdx.y == 0) {
            int t = threadIdx.y * 32 + threadIdx.x;
            for (int i = t; i < N_NODES; i += 256) g_cnt[i] = 0;
        }
        return;
    }
    __shared__ float tile[32][33];
    const float LOG2E = 1.4426950408889634f;
    int bt = blockIdx.z;
    int b = bt / T_DIM, t = bt - b * T_DIM;
    int c0 = blockIdx.y << 5, n0 = blockIdx.x << 5;
    int tx = threadIdx.x, ty = threadIdx.y;
#pragma unroll
    for (int i = 0; i < 4; i++) {
        int c = c0 + ty + i * 8;
        tile[ty + i * 8][tx] =
            nf[(((b * C_DIM + c) * T_DIM + t) * N_NODES) + n0 + tx] * LOG2E;
    }
    __syncthreads();
#pragma unroll
    for (int i = 0; i < 4; i++) {
        int n = n0 + ty + i * 8;
        g_h2[((n * BT + bt) << 6) + c0 + tx] = tile[tx][ty + i * 8];
    }
}

// ---------------- stage 0b: bucket-place edges per destination -------------
__global__ void k_build(const int* __restrict__ src, const int* __restrict__ dst) {
    int e = blockIdx.x * blockDim.x + threadIdx.x;
    int d = dst[e];
    int p = atomicAdd(&g_cnt[d], 1);
    g_epack[(d << 6) + p] = (e << 11) | src[e];
}

// ---------------- stage B: message + softmax + agg + residual ---------------
// grid (N_NODES, 3), block 256: cq = tid&15 (c-quad), grp = tid>>4 (16 groups),
// each thread owns 2 bt slots. Edge features staged in smem once per block.
// No max-pass needed: r = relu(.)*log2e in [0,~16], 2^r cannot overflow.
#define BT_PER_BLK 32
__global__ __launch_bounds__(256, 4) void k_msg(const float* __restrict__ ef) {
    __shared__ __align__(16) float s_ev[64 * 64];
    __shared__ int s_ep[64];
    __shared__ int s_cnt;
    int n = blockIdx.x;
    int tid = threadIdx.x;
    if (tid == 0) s_cnt = g_cnt[n];
    if (tid < 64) s_ep[tid] = g_epack[(n << 6) + tid];
    __syncthreads();
    int cnt = s_cnt;
    const float LOG2E = 1.4426950408889634f;
    for (int i = tid; i < (cnt << 6); i += 256) {
        int eid = s_ep[i >> 6] >> 11;
        s_ev[i] = ef[(eid << 6) + (i & 63)] * LOG2E;   // coalesced stage
    }
    __syncthreads();

    int cq = tid & 15;     // c-quad: c = 4*cq .. 4*cq+3
    int grp = tid >> 4;    // 0..15
    int bt0 = blockIdx.y * BT_PER_BLK + grp * 2;

    float4 den0 = make_float4(0, 0, 0, 0), den1 = den0;
    float4 num0 = den0, num1 = den0;

    const float4* evp = (const float4*)s_ev;   // [edge][16 quads]

#define PROC(Hq, Eq, DEN, NUM)                                            \
    {                                                                     \
        float4 v = f4add(Hq, Eq);                                         \
        float4 r = make_float4(fmaxf(v.x, 0.f), fmaxf(v.y, 0.f),          \
                               fmaxf(v.z, 0.f), fmaxf(v.w, 0.f));         \
        float4 p = make_float4(ex2f(r.x), ex2f(r.y), ex2f(r.z), ex2f(r.w)); \
        DEN = f4add(DEN, p);                                              \
        float2 nlo = f2fma(make_float2(r.x, r.y), make_float2(p.x, p.y),  \
                           make_float2(NUM.x, NUM.y));                    \
        float2 nhi = f2fma(make_float2(r.z, r.w), make_float2(p.z, p.w),  \
                           make_float2(NUM.z, NUM.w));                    \
        NUM = make_float4(nlo.x, nlo.y, nhi.x, nhi.y);                    \
    }

    int k = 0;
    for (; k + 2 <= cnt; k += 2) {
        int s0 = s_ep[k] & 2047;
        int s1 = s_ep[k + 1] & 2047;
        const float4* h0 = (const float4*)(g_h2 + (s0 * BT + bt0) * 64) + cq;
        const float4* h1 = (const float4*)(g_h2 + (s1 * BT + bt0) * 64) + cq;
        float4 a0 = h0[0], a1 = h0[16];     // bt0, bt0+1 of edge0
        float4 b0 = h1[0], b1 = h1[16];     // bt0, bt0+1 of edge1
        float4 e0 = evp[(k << 4) + cq];
        float4 e1 = evp[((k + 1) << 4) + cq];
        PROC(a0, e0, den0, num0);
        PROC(a1, e0, den1, num1);
        PROC(b0, e1, den0, num0);
        PROC(b1, e1, den1, num1);
    }
    if (k < cnt) {
        int s0 = s_ep[k] & 2047;
        const float4* h0 = (const float4*)(g_h2 + (s0 * BT + bt0) * 64) + cq;
        float4 a0 = h0[0], a1 = h0[16];
        float4 e0 = evp[(k << 4) + cq];
        PROC(a0, e0, den0, num0);
        PROC(a1, e0, den1, num1);
    }
#undef PROC

    const float LN2 = 0.6931471805599453f;
    const float EPS = 1e-7f;
    const float4* hq = (const float4*)(g_h2 + (n * BT + bt0) * 64) + cq;
    bool has = (cnt > 0);
#pragma unroll
    for (int j = 0; j < 2; j++) {
        float4 den = j ? den1 : den0;
        float4 num = j ? num1 : num0;
        float4 h = hq[j * 16];
        float4 agg = make_float4(0, 0, 0, 0);
        if (has) {
            agg.x = fmaf(num.x * rcpf(den.x), LN2, EPS);
            agg.y = fmaf(num.y * rcpf(den.y), LN2, EPS);
            agg.z = fmaf(num.z * rcpf(den.z), LN2, EPS);
            agg.w = fmaf(num.w * rcpf(den.w), LN2, EPS);
        }
        float4 o;
        o.x = fmaf(h.x, LN2, agg.x);
        o.y = fmaf(h.y, LN2, agg.y);
        o.z = fmaf(h.z, LN2, agg.z);
        o.w = fmaf(h.w, LN2, agg.w);
        // feats layout [bt][n][c]
        float4* fq = (float4*)(g_feats + (((bt0 + j) * N_NODES + n) << 6)) + cq;
        *fq = o;
    }
}

// ---------------- stage C: register-tiled GEMM, out [B,O,T,N] ---------------
// grid (16 n-blocks, 96 bt), block 128. Thread tile: 8n x 8o, with the 8 n
// split as two groups of 4 CONSECUTIVE n ({tx*4..+3} and {64+tx*4..+3}) so
// a-loads hit consecutive 16B columns -> conflict-free LDS.128 (4 wf, floor).
__global__ __launch_bounds__(128) void k_gemm(const float* __restrict__ W,
                                              const float* __restrict__ bias,
                                              float* __restrict__ out) {
    __shared__ float sA[64][128];                 // [c][n] 32KB
    __shared__ __align__(16) float sW[64 * 64];   // [c][o] 16KB
    int tid = threadIdx.x;
    int bt = blockIdx.y;
    int n0 = blockIdx.x << 7;

    // W: coalesced copy ([c][o], o contiguous); 1024 float4 over 128 threads
    {
        const float4* Wv = (const float4*)W;
        float4* sWv = (float4*)sW;
#pragma unroll
        for (int i = 0; i < 8; i++) sWv[tid + i * 128] = Wv[tid + i * 128];
    }
    // feats tile: row r = tid (128 rows), transpose into sA[c][r]
    {
        const float4* fp = (const float4*)(g_feats + ((bt * N_NODES + n0 + tid) << 6));
#pragma unroll
        for (int q = 0; q < 16; q++) {
            float4 v = fp[q];
            int c = q << 2;
            sA[c][tid] = v.x; sA[c + 1][tid] = v.y;
            sA[c + 2][tid] = v.z; sA[c + 3][tid] = v.w;
        }
    }
    __syncthreads();

    int tx = tid & 15;   // n-groups: {tx*4..+3} and {64+tx*4..+3}
    int ty = tid >> 4;   // o-octet: o = ty*8 .. +7

    float2 acc[8][4];
#pragma unroll
    for (int i = 0; i < 8; i++)
#pragma unroll
        for (int p = 0; p < 4; p++) acc[i][p] = make_float2(0.f, 0.f);

    const float4* sWv4 = (const float4*)sW;
    // pipeline prologue: load c=0 operands (conflict-free addresses)
    float4 a0 = *(const float4*)&sA[0][tx << 2];
    float4 a1 = *(const float4*)&sA[0][64 + (tx << 2)];
    float4 w0 = sWv4[(ty << 1)];
    float4 w1 = sWv4[(ty << 1) + 1];

#pragma unroll 4
    for (int c = 0; c < 64; c++) {
        int cn = (c + 1) & 63;
        float4 na0 = *(const float4*)&sA[cn][tx << 2];
        float4 na1 = *(const float4*)&sA[cn][64 + (tx << 2)];
        float4 nw0 = sWv4[(cn << 4) + (ty << 1)];
        float4 nw1 = sWv4[(cn << 4) + (ty << 1) + 1];

        float2 wp[4] = {{w0.x, w0.y}, {w0.z, w0.w}, {w1.x, w1.y}, {w1.z, w1.w}};
        float av[8] = {a0.x, a0.y, a0.z, a0.w, a1.x, a1.y, a1.z, a1.w};
#pragma unroll
        for (int i = 0; i < 8; i++) {
            float2 ad = make_float2(av[i], av[i]);
#pragma unroll
            for (int p = 0; p < 4; p++) acc[i][p] = f2fma(ad, wp[p], acc[i][p]);
        }
        a0 = na0; a1 = na1; w0 = nw0; w1 = nw1;
    }

    // epilogue: +bias, STG.128 per n-group per output o
    int b = bt / T_DIM, t = bt - b * T_DIM;
    float* obase = out + ((b * OUT_DIM) * T_DIM + t) * N_NODES + n0 + (tx << 2);
#pragma unroll
    for (int p = 0; p < 4; p++) {
        int oe = (ty << 3) + (p << 1);
        float b0 = __ldg(bias + oe), b1 = __ldg(bias + oe + 1);
        float4 v0a, v0b, v1a, v1b;
        v0a.x = acc[0][p].x + b0; v0a.y = acc[1][p].x + b0;
        v0a.z = acc[2][p].x + b0; v0a.w = acc[3][p].x + b0;
        v0b.x = acc[4][p].x + b0; v0b.y = acc[5][p].x + b0;
        v0b.z = acc[6][p].x + b0; v0b.w = acc[7][p].x + b0;
        v1a.x = acc[0][p].y + b1; v1a.y = acc[1][p].y + b1;
        v1a.z = acc[2][p].y + b1; v1a.w = acc[3][p].y + b1;
        v1b.x = acc[4][p].y + b1; v1b.y = acc[5][p].y + b1;
        v1b.z = acc[6][p].y + b1; v1b.w = acc[7][p].y + b1;
        long long so = (long long)oe * (T_DIM * N_NODES);
        long long s1 = (long long)(oe + 1) * (T_DIM * N_NODES);
        *(float4*)(obase + so) = v0a;          // n-group lo
        *(float4*)(obase + so + 64) = v0b;     // n-group hi (+64 n)
        *(float4*)(obase + s1) = v1a;
        *(float4*)(obase + s1 + 64) = v1b;
    }
}

// ---------------- launch ----------------
extern "C" void kernel_launch(void* const* d_in, const int* in_sizes, int n_in,
                              void* d_out, int out_size) {
    const float* nf   = (const float*)d_in[0];  // node_feats [B,C,T,N]
    const float* ef   = (const float*)d_in[1];  // edge_feat  [E,1,1,C]
    const int*   src  = (const int*)d_in[2];
    const int*   dst  = (const int*)d_in[3];
    const float* W    = (const float*)d_in[4];
    const float* bvec = (const float*)d_in[5];
    float* out = (float*)d_out;

    k_transpose<<<dim3(N_NODES / 32, C_DIM / 32, BT + 1), dim3(32, 8)>>>(nf);
    k_build<<<N_EDGES / 256, 256>>>(src, dst);
    k_msg<<<dim3(N_NODES, 3), 256>>>(ef);
    k_gemm<<<dim3(N_NODES / 128, BT), 128>>>(W, bvec, out);
}

// round 9
// speedup vs baseline: 1.1061x; 1.0324x over previous
#include <cuda_runtime.h>
#include <cstdint>

#define N_NODES 2048
#define N_EDGES 16384
#define B_DIM 8
#define C_DIM 64
#define T_DIM 12
#define BT 96                 // B*T
#define OUT_DIM 64

// ---------------- scratch (static __device__, no allocation) ----------------
__device__ float g_h2[N_NODES * BT * C_DIM];     // h * log2(e), [n][bt][c]
__device__ float g_feats[BT * N_NODES * C_DIM];  // h + agg,     [bt][n][c]
__device__ int   g_cnt[N_NODES];
__device__ int   g_epack[N_NODES * 64];          // (eid<<11)|src per dst slot

// ---------------- packed f32x2 helpers ----------------
union F2U { float2 f; unsigned long long u; };
__device__ __forceinline__ float2 f2add(float2 a, float2 b) {
    F2U A, B2, D; A.f = a; B2.f = b;
    asm("add.rn.f32x2 %0, %1, %2;" : "=l"(D.u) : "l"(A.u), "l"(B2.u));
    return D.f;
}
__device__ __forceinline__ float2 f2fma(float2 a, float2 b, float2 c) {
    F2U A, B2, C2, D; A.f = a; B2.f = b; C2.f = c;
    asm("fma.rn.f32x2 %0, %1, %2, %3;" : "=l"(D.u) : "l"(A.u), "l"(B2.u), "l"(C2.u));
    return D.f;
}
__device__ __forceinline__ float4 f4add(float4 a, float4 b) {
    float2 lo = f2add(make_float2(a.x, a.y), make_float2(b.x, b.y));
    float2 hi = f2add(make_float2(a.z, a.w), make_float2(b.z, b.w));
    return make_float4(lo.x, lo.y, hi.x, hi.y);
}
__device__ __forceinline__ float ex2f(float x) {
    float r; asm("ex2.approx.f32 %0, %1;" : "=f"(r) : "f"(x)); return r;
}
__device__ __forceinline__ float rcpf(float x) {
    float r; asm("rcp.approx.f32 %0, %1;" : "=f"(r) : "f"(x)); return r;
}
__device__ __forceinline__ uint32_t smem_u32(const void* p) {
    uint32_t a;
    asm("{ .reg .u64 t; cvta.to.shared.u64 t, %1; cvt.u32.u64 %0, t; }"
        : "=r"(a) : "l"(p));
    return a;
}
// split two fp32 into packed bf16x2 hi + lo (hi = rn(x), lo = rn(x - hi))
__device__ __forceinline__ void bf16_split2(float a, float b,
                                            uint32_t& hp, uint32_t& lp) {
    asm("cvt.rn.bf16x2.f32 %0, %1, %2;" : "=r"(hp) : "f"(b), "f"(a));
    float fa = __uint_as_float(hp << 16);
    float fb = __uint_as_float(hp & 0xffff0000u);
    float ra = a - fa, rb = b - fb;
    asm("cvt.rn.bf16x2.f32 %0, %1, %2;" : "=r"(lp) : "f"(rb), "f"(ra));
}
#define SW128(off) ((off) ^ (((off) >> 3) & 0x70))

// ---------------- stage A: transpose [B,C,T,N] -> [N,BT,C] (*log2e),
//                  plus (extra z-slice) counter zeroing ----------------------
__global__ void k_transpose(const float* __restrict__ nf) {
    if (blockIdx.z == BT) {
        if (blockIdx.x == 0 && blockIdx.y == 0) {
            int t = threadIdx.y * 32 + threadIdx.x;
            for (int i = t; i < N_NODES; i += 256) g_cnt[i] = 0;
        }
        return;
    }
    __shared__ float tile[32][33];
    const float LOG2E = 1.4426950408889634f;
    int bt = blockIdx.z;
    int b = bt / T_DIM, t = bt - b * T_DIM;
    int c0 = blockIdx.y << 5, n0 = blockIdx.x << 5;
    int tx = threadIdx.x, ty = threadIdx.y;
#pragma unroll
    for (int i = 0; i < 4; i++) {
        int c = c0 + ty + i * 8;
        tile[ty + i * 8][tx] =
            nf[(((b * C_DIM + c) * T_DIM + t) * N_NODES) + n0 + tx] * LOG2E;
    }
    __syncthreads();
#pragma unroll
    for (int i = 0; i < 4; i++) {
        int n = n0 + ty + i * 8;
        g_h2[((n * BT + bt) << 6) + c0 + tx] = tile[tx][ty + i * 8];
    }
}

// ---------------- stage 0b: bucket-place edges per destination -------------
__global__ void k_build(const int* __restrict__ src, const int* __restrict__ dst) {
    int e = blockIdx.x * blockDim.x + threadIdx.x;
    int d = dst[e];
    int p = atomicAdd(&g_cnt[d], 1);
    g_epack[(d << 6) + p] = (e << 11) | src[e];
}

// ---------------- stage B: message + softmax + agg + residual ---------------
#define BT_PER_BLK 32
__global__ __launch_bounds__(256, 4) void k_msg(const float* __restrict__ ef) {
    __shared__ __align__(16) float s_ev[64 * 64];
    __shared__ int s_ep[64];
    __shared__ int s_cnt;
    int n = blockIdx.x;
    int tid = threadIdx.x;
    if (tid == 0) s_cnt = g_cnt[n];
    if (tid < 64) s_ep[tid] = g_epack[(n << 6) + tid];
    __syncthreads();
    int cnt = s_cnt;
    const float LOG2E = 1.4426950408889634f;
    for (int i = tid; i < (cnt << 6); i += 256) {
        int eid = s_ep[i >> 6] >> 11;
        s_ev[i] = ef[(eid << 6) + (i & 63)] * LOG2E;
    }
    __syncthreads();

    int cq = tid & 15;
    int grp = tid >> 4;
    int bt0 = blockIdx.y * BT_PER_BLK + grp * 2;

    float4 den0 = make_float4(0, 0, 0, 0), den1 = den0;
    float4 num0 = den0, num1 = den0;

    const float4* evp = (const float4*)s_ev;

#define PROC(Hq, Eq, DEN, NUM)                                            \
    {                                                                     \
        float4 v = f4add(Hq, Eq);                                         \
        float4 r = make_float4(fmaxf(v.x, 0.f), fmaxf(v.y, 0.f),          \
                               fmaxf(v.z, 0.f), fmaxf(v.w, 0.f));         \
        float4 p = make_float4(ex2f(r.x), ex2f(r.y), ex2f(r.z), ex2f(r.w)); \
        DEN = f4add(DEN, p);                                              \
        float2 nlo = f2fma(make_float2(r.x, r.y), make_float2(p.x, p.y),  \
                           make_float2(NUM.x, NUM.y));                    \
        float2 nhi = f2fma(make_float2(r.z, r.w), make_float2(p.z, p.w),  \
                           make_float2(NUM.z, NUM.w));                    \
        NUM = make_float4(nlo.x, nlo.y, nhi.x, nhi.y);                    \
    }

    int k = 0;
    for (; k + 2 <= cnt; k += 2) {
        int s0 = s_ep[k] & 2047;
        int s1 = s_ep[k + 1] & 2047;
        const float4* h0 = (const float4*)(g_h2 + (s0 * BT + bt0) * 64) + cq;
        const float4* h1 = (const float4*)(g_h2 + (s1 * BT + bt0) * 64) + cq;
        float4 a0 = h0[0], a1 = h0[16];
        float4 b0 = h1[0], b1 = h1[16];
        float4 e0 = evp[(k << 4) + cq];
        float4 e1 = evp[((k + 1) << 4) + cq];
        PROC(a0, e0, den0, num0);
        PROC(a1, e0, den1, num1);
        PROC(b0, e1, den0, num0);
        PROC(b1, e1, den1, num1);
    }
    if (k < cnt) {
        int s0 = s_ep[k] & 2047;
        const float4* h0 = (const float4*)(g_h2 + (s0 * BT + bt0) * 64) + cq;
        float4 a0 = h0[0], a1 = h0[16];
        float4 e0 = evp[(k << 4) + cq];
        PROC(a0, e0, den0, num0);
        PROC(a1, e0, den1, num1);
    }
#undef PROC

    const float LN2 = 0.6931471805599453f;
    const float EPS = 1e-7f;
    const float4* hq = (const float4*)(g_h2 + (n * BT + bt0) * 64) + cq;
    bool has = (cnt > 0);
#pragma unroll
    for (int j = 0; j < 2; j++) {
        float4 den = j ? den1 : den0;
        float4 num = j ? num1 : num0;
        float4 h = hq[j * 16];
        float4 agg = make_float4(0, 0, 0, 0);
        if (has) {
            agg.x = fmaf(num.x * rcpf(den.x), LN2, EPS);
            agg.y = fmaf(num.y * rcpf(den.y), LN2, EPS);
            agg.z = fmaf(num.z * rcpf(den.z), LN2, EPS);
            agg.w = fmaf(num.w * rcpf(den.w), LN2, EPS);
        }
        float4 o;
        o.x = fmaf(h.x, LN2, agg.x);
        o.y = fmaf(h.y, LN2, agg.y);
        o.z = fmaf(h.z, LN2, agg.z);
        o.w = fmaf(h.w, LN2, agg.w);
        float4* fq = (float4*)(g_feats + (((bt0 + j) * N_NODES + n) << 6)) + cq;
        *fq = o;
    }
}

// ---------------- stage C: HMMA bf16 GEMM (mma.sync), out [B,O,T,N] ---------
// Block tile 128n x 64o x 64c, 4 warps (each 32n x 64o).
// A (feats) and B (W^T, [o][c]) in SW128-swizzled bf16 hi/lo smem (48KB).
// D = Ah*Bh + Al*Bh + Ah*Bl  (fp32 accum; missing Al*Bl term ~2^-16 rel).
#define SM_AH 0
#define SM_AL 16384
#define SM_BH 32768
#define SM_BL 40960

__device__ __forceinline__ void ldsm4(uint32_t* r, uint32_t addr) {
    asm volatile("ldmatrix.sync.aligned.m8n8.x4.shared.b16 {%0,%1,%2,%3}, [%4];"
                 : "=r"(r[0]), "=r"(r[1]), "=r"(r[2]), "=r"(r[3]) : "r"(addr));
}
__device__ __forceinline__ void mma16816(float* d, const uint32_t* a,
                                         uint32_t b0, uint32_t b1) {
    asm volatile(
        "mma.sync.aligned.m16n8k16.row.col.f32.bf16.bf16.f32 "
        "{%0,%1,%2,%3}, {%4,%5,%6,%7}, {%8,%9}, {%0,%1,%2,%3};"
        : "+f"(d[0]), "+f"(d[1]), "+f"(d[2]), "+f"(d[3])
        : "r"(a[0]), "r"(a[1]), "r"(a[2]), "r"(a[3]), "r"(b0), "r"(b1));
}

__global__ __launch_bounds__(128) void k_gemm_mma(const float* __restrict__ W,
                                                  const float* __restrict__ bias,
                                                  float* __restrict__ out) {
    __shared__ __align__(1024) uint8_t smem[49152];
    uint32_t sb = smem_u32(smem);
    int tid = threadIdx.x;
    int bt = blockIdx.y;
    int n0 = blockIdx.x << 7;

    // ---- A: feats row tid (128 rows x 64c) -> bf16 hi/lo, SW128 ----
    {
        const float4* fp = (const float4*)(g_feats + ((bt * N_NODES + n0 + tid) << 6));
#pragma unroll
        for (int i = 0; i < 8; i++) {
            float4 x = fp[2 * i], y = fp[2 * i + 1];
            uint32_t h0, h1, h2, h3, l0, l1, l2, l3;
            bf16_split2(x.x, x.y, h0, l0);
            bf16_split2(x.z, x.w, h1, l1);
            bf16_split2(y.x, y.y, h2, l2);
            bf16_split2(y.z, y.w, h3, l3);
            uint32_t off = SW128((uint32_t)(tid * 128 + i * 16));
            *(uint4*)(smem + SM_AH + off) = make_uint4(h0, h1, h2, h3);
            *(uint4*)(smem + SM_AL + off) = make_uint4(l0, l1, l2, l3);
        }
    }
    // ---- B: B[o][c] = W[c][o] -> bf16 hi/lo, SW128 (64 rows x 64c) ----
    {
        int o = tid & 63, half = tid >> 6;
#pragma unroll
        for (int j = 0; j < 16; j++) {
            int c = (half << 5) + (j << 1);
            float w0 = W[c * 64 + o];
            float w1 = W[(c + 1) * 64 + o];
            uint32_t hp, lp;
            bf16_split2(w0, w1, hp, lp);
            uint32_t off = SW128((uint32_t)(o * 128 + c * 2));
            *(uint32_t*)(smem + SM_BH + off) = hp;
            *(uint32_t*)(smem + SM_BL + off) = lp;
        }
    }
    __syncthreads();

    int w = tid >> 5, lane = tid & 31;
    int lr = (lane & 7) + ((lane >> 3) & 1) * 8;  // row within 16-row frag
    int lc = (lane >> 4) * 16;                    // 16B half select

    float acc[2][8][4];
#pragma unroll
    for (int mi = 0; mi < 2; mi++)
#pragma unroll
        for (int ni = 0; ni < 8; ni++)
#pragma unroll
            for (int q = 0; q < 4; q++) acc[mi][ni][q] = 0.f;

    const uint32_t aoff[3] = {SM_AH, SM_AL, SM_AH};
    const uint32_t boff[3] = {SM_BH, SM_BH, SM_BL};

#pragma unroll
    for (int pass = 0; pass < 3; pass++) {
        uint32_t Ab = sb + aoff[pass];
        uint32_t Bb = sb + boff[pass];
#pragma unroll
        for (int k = 0; k < 4; k++) {
            int cb = k * 32 + lc;  // column byte offset
            uint32_t a[2][4];
#pragma unroll
            for (int mi = 0; mi < 2; mi++) {
                uint32_t row = w * 32 + mi * 16 + lr;
                ldsm4(a[mi], Ab + SW128(row * 128 + cb));
            }
            uint32_t b[4][4];
#pragma unroll
            for (int p = 0; p < 4; p++) {
                uint32_t row = p * 16 + lr;
                ldsm4(b[p], Bb + SW128(row * 128 + cb));
            }
#pragma unroll
            for (int mi = 0; mi < 2; mi++)
#pragma unroll
                for (int ni = 0; ni < 8; ni++)
                    mma16816(acc[mi][ni], a[mi],
                             b[ni >> 1][ni & 1], b[ni >> 1][2 + (ni & 1)]);
        }
    }

    // ---- epilogue: direct STG.32; 8-lane groups write 32B sectors ----
    int g = lane >> 2, t4 = lane & 3;
    int b = bt / T_DIM, tt = bt - b * T_DIM;
    const long long OSTRIDE = (long long)T_DIM * N_NODES;  // per-o stride
    float* ob = out + ((long long)(b * OUT_DIM) * T_DIM + tt) * N_NODES;
#pragma unroll
    for (int mi = 0; mi < 2; mi++) {
        int n = n0 + w * 32 + mi * 16 + g;
#pragma unroll
        for (int ni = 0; ni < 8; ni++) {
            int o0 = (ni << 3) + (t4 << 1);
            float b0 = __ldg(bias + o0), b1 = __ldg(bias + o0 + 1);
            float* p0 = ob + (long long)o0 * OSTRIDE + n;
            float* p1 = p0 + OSTRIDE;
            p0[0] = acc[mi][ni][0] + b0;
            p1[0] = acc[mi][ni][1] + b1;
            p0[8] = acc[mi][ni][2] + b0;
            p1[8] = acc[mi][ni][3] + b1;
        }
    }
}

// ---------------- launch ----------------
extern "C" void kernel_launch(void* const* d_in, const int* in_sizes, int n_in,
                              void* d_out, int out_size) {
    const float* nf   = (const float*)d_in[0];  // node_feats [B,C,T,N]
    const float* ef   = (const float*)d_in[1];  // edge_feat  [E,1,1,C]
    const int*   src  = (const int*)d_in[2];
    const int*   dst  = (const int*)d_in[3];
    const float* W    = (const float*)d_in[4];
    const float* bvec = (const float*)d_in[5];
    float* out = (float*)d_out;

    k_transpose<<<dim3(N_NODES / 32, C_DIM / 32, BT + 1), dim3(32, 8)>>>(nf);
    k_build<<<N_EDGES / 256, 256>>>(src, dst);
    k_msg<<<dim3(N_NODES, 3), 256>>>(ef);
    k_gemm_mma<<<dim3(N_NODES / 128, BT), 128>>>(W, bvec, out);
}

// round 10
// speedup vs baseline: 1.2116x; 1.0954x over previous
#include <cuda_runtime.h>
#include <cstdint>

#define N_NODES 2048
#define N_EDGES 16384
#define B_DIM 8
#define C_DIM 64
#define T_DIM 12
#define BT 96                 // B*T
#define OUT_DIM 64

// ---------------- scratch (static __device__, no allocation) ----------------
__device__ float g_h2[N_NODES * BT * C_DIM];     // h * log2(e), [n][bt][c]
// feats pre-split to bf16 hi/lo, pre-SW128-swizzled per 128B row: [bt][n][128B]
__device__ __align__(16) uint8_t g_fh[BT * N_NODES * 128];
__device__ __align__(16) uint8_t g_fl[BT * N_NODES * 128];
// W^T pre-split bf16 hi/lo, pre-swizzled: [o][128B]
__device__ __align__(16) uint8_t g_wh[OUT_DIM * 128];
__device__ __align__(16) uint8_t g_wl[OUT_DIM * 128];
__device__ int   g_cnt[N_NODES];
__device__ int   g_epack[N_NODES * 64];          // (eid<<11)|src per dst slot

// ---------------- packed f32x2 helpers ----------------
union F2U { float2 f; unsigned long long u; };
__device__ __forceinline__ float2 f2add(float2 a, float2 b) {
    F2U A, B2, D; A.f = a; B2.f = b;
    asm("add.rn.f32x2 %0, %1, %2;" : "=l"(D.u) : "l"(A.u), "l"(B2.u));
    return D.f;
}
__device__ __forceinline__ float2 f2fma(float2 a, float2 b, float2 c) {
    F2U A, B2, C2, D; A.f = a; B2.f = b; C2.f = c;
    asm("fma.rn.f32x2 %0, %1, %2, %3;" : "=l"(D.u) : "l"(A.u), "l"(B2.u), "l"(C2.u));
    return D.f;
}
__device__ __forceinline__ float4 f4add(float4 a, float4 b) {
    float2 lo = f2add(make_float2(a.x, a.y), make_float2(b.x, b.y));
    float2 hi = f2add(make_float2(a.z, a.w), make_float2(b.z, b.w));
    return make_float4(lo.x, lo.y, hi.x, hi.y);
}
__device__ __forceinline__ float ex2f(float x) {
    float r; asm("ex2.approx.f32 %0, %1;" : "=f"(r) : "f"(x)); return r;
}
__device__ __forceinline__ float rcpf(float x) {
    float r; asm("rcp.approx.f32 %0, %1;" : "=f"(r) : "f"(x)); return r;
}
__device__ __forceinline__ uint32_t smem_u32(const void* p) {
    uint32_t a;
    asm("{ .reg .u64 t; cvta.to.shared.u64 t, %1; cvt.u32.u64 %0, t; }"
        : "=r"(a) : "l"(p));
    return a;
}
// split two fp32 into packed bf16x2 hi + lo (hi = rn(x), lo = rn(x - hi))
__device__ __forceinline__ void bf16_split2(float a, float b,
                                            uint32_t& hp, uint32_t& lp) {
    asm("cvt.rn.bf16x2.f32 %0, %1, %2;" : "=r"(hp) : "f"(b), "f"(a));
    float fa = __uint_as_float(hp << 16);
    float fb = __uint_as_float(hp & 0xffff0000u);
    float ra = a - fa, rb = b - fb;
    asm("cvt.rn.bf16x2.f32 %0, %1, %2;" : "=r"(lp) : "f"(rb), "f"(ra));
}
#define SW128(off) ((off) ^ (((off) >> 3) & 0x70))

// ---------------- stage A: transpose [B,C,T,N] -> [N,BT,C] (*log2e),
// extra z-slice: zero counters + prepare pre-swizzled bf16 hi/lo W^T ---------
__global__ void k_transpose(const float* __restrict__ nf,
                            const float* __restrict__ W) {
    if (blockIdx.z == BT) {
        if (blockIdx.x == 0 && blockIdx.y == 0) {
            int t = threadIdx.y * 32 + threadIdx.x;
            for (int i = t; i < N_NODES; i += 256) g_cnt[i] = 0;
            // B[o][c] = W[c][o], bf16 hi/lo pairs, SW128-swizzled rows
            for (int i = t; i < 2048; i += 256) {   // i = o*32 + cp
                int o = i >> 5, cp = i & 31;
                float w0 = W[(2 * cp) * 64 + o];
                float w1 = W[(2 * cp + 1) * 64 + o];
                uint32_t hp, lp;
                bf16_split2(w0, w1, hp, lp);
                uint32_t off = SW128((uint32_t)(o * 128 + cp * 4));
                *(uint32_t*)(g_wh + off) = hp;
                *(uint32_t*)(g_wl + off) = lp;
            }
        }
        return;
    }
    __shared__ float tile[32][33];
    const float LOG2E = 1.4426950408889634f;
    int bt = blockIdx.z;
    int b = bt / T_DIM, t = bt - b * T_DIM;
    int c0 = blockIdx.y << 5, n0 = blockIdx.x << 5;
    int tx = threadIdx.x, ty = threadIdx.y;
#pragma unroll
    for (int i = 0; i < 4; i++) {
        int c = c0 + ty + i * 8;
        tile[ty + i * 8][tx] =
            nf[(((b * C_DIM + c) * T_DIM + t) * N_NODES) + n0 + tx] * LOG2E;
    }
    __syncthreads();
#pragma unroll
    for (int i = 0; i < 4; i++) {
        int n = n0 + ty + i * 8;
        g_h2[((n * BT + bt) << 6) + c0 + tx] = tile[tx][ty + i * 8];
    }
}

// ---------------- stage 0b: bucket-place edges per destination -------------
__global__ void k_build(const int* __restrict__ src, const int* __restrict__ dst) {
    int e = blockIdx.x * blockDim.x + threadIdx.x;
    int d = dst[e];
    int p = atomicAdd(&g_cnt[d], 1);
    g_epack[(d << 6) + p] = (e << 11) | src[e];
}

// ---------------- stage B: message + softmax + agg + residual ---------------
// Output feats directly as bf16 hi/lo, pre-swizzled for the MMA gemm.
#define BT_PER_BLK 32
__global__ __launch_bounds__(256, 4) void k_msg(const float* __restrict__ ef) {
    __shared__ __align__(16) float s_ev[64 * 64];
    __shared__ int s_ep[64];
    __shared__ int s_cnt;
    int n = blockIdx.x;
    int tid = threadIdx.x;
    if (tid == 0) s_cnt = g_cnt[n];
    if (tid < 64) s_ep[tid] = g_epack[(n << 6) + tid];
    __syncthreads();
    int cnt = s_cnt;
    const float LOG2E = 1.4426950408889634f;
    for (int i = tid; i < (cnt << 6); i += 256) {
        int eid = s_ep[i >> 6] >> 11;
        s_ev[i] = ef[(eid << 6) + (i & 63)] * LOG2E;
    }
    __syncthreads();

    int cq = tid & 15;
    int grp = tid >> 4;
    int bt0 = blockIdx.y * BT_PER_BLK + grp * 2;

    float4 den0 = make_float4(0, 0, 0, 0), den1 = den0;
    float4 num0 = den0, num1 = den0;

    const float4* evp = (const float4*)s_ev;

#define PROC(Hq, Eq, DEN, NUM)                                            \
    {                                                                     \
        float4 v = f4add(Hq, Eq);                                         \
        float4 r = make_float4(fmaxf(v.x, 0.f), fmaxf(v.y, 0.f),          \
                               fmaxf(v.z, 0.f), fmaxf(v.w, 0.f));         \
        float4 p = make_float4(ex2f(r.x), ex2f(r.y), ex2f(r.z), ex2f(r.w)); \
        DEN = f4add(DEN, p);                                              \
        float2 nlo = f2fma(make_float2(r.x, r.y), make_float2(p.x, p.y),  \
                           make_float2(NUM.x, NUM.y));                    \
        float2 nhi = f2fma(make_float2(r.z, r.w), make_float2(p.z, p.w),  \
                           make_float2(NUM.z, NUM.w));                    \
        NUM = make_float4(nlo.x, nlo.y, nhi.x, nhi.y);                    \
    }

    int k = 0;
    for (; k + 2 <= cnt; k += 2) {
        int s0 = s_ep[k] & 2047;
        int s1 = s_ep[k + 1] & 2047;
        const float4* h0 = (const float4*)(g_h2 + (s0 * BT + bt0) * 64) + cq;
        const float4* h1 = (const float4*)(g_h2 + (s1 * BT + bt0) * 64) + cq;
        float4 a0 = h0[0], a1 = h0[16];
        float4 b0 = h1[0], b1 = h1[16];
        float4 e0 = evp[(k << 4) + cq];
        float4 e1 = evp[((k + 1) << 4) + cq];
        PROC(a0, e0, den0, num0);
        PROC(a1, e0, den1, num1);
        PROC(b0, e1, den0, num0);
        PROC(b1, e1, den1, num1);
    }
    if (k < cnt) {
        int s0 = s_ep[k] & 2047;
        const float4* h0 = (const float4*)(g_h2 + (s0 * BT + bt0) * 64) + cq;
        float4 a0 = h0[0], a1 = h0[16];
        float4 e0 = evp[(k << 4) + cq];
        PROC(a0, e0, den0, num0);
        PROC(a1, e0, den1, num1);
    }
#undef PROC

    const float LN2 = 0.6931471805599453f;
    const float EPS = 1e-7f;
    const float4* hq = (const float4*)(g_h2 + (n * BT + bt0) * 64) + cq;
    bool has = (cnt > 0);
    uint32_t chunk = ((uint32_t)(cq * 8)) ^ (((uint32_t)n & 7) << 4);
#pragma unroll
    for (int j = 0; j < 2; j++) {
        float4 den = j ? den1 : den0;
        float4 num = j ? num1 : num0;
        float4 h = hq[j * 16];
        float4 agg = make_float4(0, 0, 0, 0);
        if (has) {
            agg.x = fmaf(num.x * rcpf(den.x), LN2, EPS);
            agg.y = fmaf(num.y * rcpf(den.y), LN2, EPS);
            agg.z = fmaf(num.z * rcpf(den.z), LN2, EPS);
            agg.w = fmaf(num.w * rcpf(den.w), LN2, EPS);
        }
        float4 o;
        o.x = fmaf(h.x, LN2, agg.x);
        o.y = fmaf(h.y, LN2, agg.y);
        o.z = fmaf(h.z, LN2, agg.z);
        o.w = fmaf(h.w, LN2, agg.w);
        // split to bf16 hi/lo, store pre-swizzled [bt][n][128B]
        uint32_t hx, lx, hy, ly;
        bf16_split2(o.x, o.y, hx, lx);
        bf16_split2(o.z, o.w, hy, ly);
        size_t base = ((size_t)(bt0 + j) * N_NODES + n) * 128 + chunk;
        *(uint2*)(g_fh + base) = make_uint2(hx, hy);
        *(uint2*)(g_fl + base) = make_uint2(lx, ly);
    }
}

// ---------------- stage C: HMMA bf16 GEMM (mma.sync), out [B,O,T,N] ---------
// Block tile 128n x 64o x 64c, 4 warps. A/B arrive pre-split + pre-swizzled;
// prologue is pure coalesced copy. D = Ah*Bh + Al*Bh + Ah*Bl (fp32 accum).
// Epilogue stages through smem (pitch 132, conflict-free) -> coalesced STG.128.
#define SM_AH 0
#define SM_AL 16384
#define SM_BH 32768
#define SM_BL 40960

__device__ __forceinline__ void ldsm4(uint32_t* r, uint32_t addr) {
    asm volatile("ldmatrix.sync.aligned.m8n8.x4.shared.b16 {%0,%1,%2,%3}, [%4];"
                 : "=r"(r[0]), "=r"(r[1]), "=r"(r[2]), "=r"(r[3]) : "r"(addr));
}
__device__ __forceinline__ void mma16816(float* d, const uint32_t* a,
                                         uint32_t b0, uint32_t b1) {
    asm volatile(
        "mma.sync.aligned.m16n8k16.row.col.f32.bf16.bf16.f32 "
        "{%0,%1,%2,%3}, {%4,%5,%6,%7}, {%8,%9}, {%0,%1,%2,%3};"
        : "+f"(d[0]), "+f"(d[1]), "+f"(d[2]), "+f"(d[3])
        : "r"(a[0]), "r"(a[1]), "r"(a[2]), "r"(a[3]), "r"(b0), "r"(b1));
}

__global__ __launch_bounds__(128) void k_gemm_mma(const float* __restrict__ bias,
                                                  float* __restrict__ out) {
    __shared__ __align__(1024) uint8_t smem[49152];
    uint32_t sb = smem_u32(smem);
    int tid = threadIdx.x;
    int bt = blockIdx.y;
    int n0 = blockIdx.x << 7;

    // ---- prologue: pure coalesced copies (pre-swizzled in gmem) ----
    {
        const uint4* sH = (const uint4*)(g_fh + ((size_t)bt * N_NODES + n0) * 128);
        const uint4* sL = (const uint4*)(g_fl + ((size_t)bt * N_NODES + n0) * 128);
        uint4* dH = (uint4*)(smem + SM_AH);
        uint4* dL = (uint4*)(smem + SM_AL);
#pragma unroll
        for (int i = 0; i < 8; i++) {
            dH[tid + i * 128] = sH[tid + i * 128];
            dL[tid + i * 128] = sL[tid + i * 128];
        }
        const uint4* wH = (const uint4*)g_wh;
        const uint4* wL = (const uint4*)g_wl;
        uint4* bH = (uint4*)(smem + SM_BH);
        uint4* bL = (uint4*)(smem + SM_BL);
#pragma unroll
        for (int i = 0; i < 4; i++) {
            bH[tid + i * 128] = wH[tid + i * 128];
            bL[tid + i * 128] = wL[tid + i * 128];
        }
    }
    __syncthreads();

    int w = tid >> 5, lane = tid & 31;
    int lr = (lane & 7) + ((lane >> 3) & 1) * 8;  // row within 16-row frag
    int lc = (lane >> 4) * 16;                    // 16B half select

    float acc[2][8][4];
#pragma unroll
    for (int mi = 0; mi < 2; mi++)
#pragma unroll
        for (int ni = 0; ni < 8; ni++)
#pragma unroll
            for (int q = 0; q < 4; q++) acc[mi][ni][q] = 0.f;

    const uint32_t aoff[3] = {SM_AH, SM_AL, SM_AH};
    const uint32_t boff[3] = {SM_BH, SM_BH, SM_BL};

#pragma unroll
    for (int pass = 0; pass < 3; pass++) {
        uint32_t Ab = sb + aoff[pass];
        uint32_t Bb = sb + boff[pass];
#pragma unroll
        for (int k = 0; k < 4; k++) {
            int cb = k * 32 + lc;  // column byte offset
            uint32_t a[2][4];
#pragma unroll
            for (int mi = 0; mi < 2; mi++) {
                uint32_t row = w * 32 + mi * 16 + lr;
                ldsm4(a[mi], Ab + SW128(row * 128 + cb));
            }
            uint32_t b[4][4];
#pragma unroll
            for (int p = 0; p < 4; p++) {
                uint32_t row = p * 16 + lr;
                ldsm4(b[p], Bb + SW128(row * 128 + cb));
            }
#pragma unroll
            for (int mi = 0; mi < 2; mi++)
#pragma unroll
                for (int ni = 0; ni < 8; ni++)
                    mma16816(acc[mi][ni], a[mi],
                             b[ni >> 1][ni & 1], b[ni >> 1][2 + (ni & 1)]);
        }
    }

    // ---- epilogue: stage to smem (pitch 132 floats, conflict-free), then
    //      fully-coalesced STG.128 with bias add ----
    __syncthreads();
    float* so = (float*)smem;   // 64 * 132 * 4 = 33792 B <= 49152
    int g = lane >> 2, t4 = lane & 3;
#pragma unroll
    for (int mi = 0; mi < 2; mi++) {
        int n_lo = w * 32 + mi * 16 + g;
#pragma unroll
        for (int ni = 0; ni < 8; ni++) {
            int o0 = (ni << 3) + (t4 << 1);
            so[o0 * 132 + n_lo] = acc[mi][ni][0];
            so[(o0 + 1) * 132 + n_lo] = acc[mi][ni][1];
            so[o0 * 132 + n_lo + 8] = acc[mi][ni][2];
            so[(o0 + 1) * 132 + n_lo + 8] = acc[mi][ni][3];
        }
    }
    __syncthreads();

    int b = bt / T_DIM, tt = bt - b * T_DIM;
    const long long OSTRIDE = (long long)T_DIM * N_NODES;
    float* ob = out + ((long long)(b * OUT_DIM) * T_DIM + tt) * N_NODES + n0;
#pragma unroll
    for (int it = 0; it < 16; it++) {
        int idx = it * 128 + tid;         // 0..2047 float4 units
        int o = idx >> 5, q4 = idx & 31;
        float4 v = *(const float4*)&so[o * 132 + (q4 << 2)];
        float bb = __ldg(bias + o);
        v.x += bb; v.y += bb; v.z += bb; v.w += bb;
        *(float4*)(ob + (long long)o * OSTRIDE + (q4 << 2)) = v;
    }
}

// ---------------- launch ----------------
extern "C" void kernel_launch(void* const* d_in, const int* in_sizes, int n_in,
                              void* d_out, int out_size) {
    const float* nf   = (const float*)d_in[0];  // node_feats [B,C,T,N]
    const float* ef   = (const float*)d_in[1];  // edge_feat  [E,1,1,C]
    const int*   src  = (const int*)d_in[2];
    const int*   dst  = (const int*)d_in[3];
    const float* W    = (const float*)d_in[4];
    const float* bvec = (const float*)d_in[5];
    float* out = (float*)d_out;

    k_transpose<<<dim3(N_NODES / 32, C_DIM / 32, BT + 1), dim3(32, 8)>>>(nf, W);
    k_build<<<N_EDGES / 256, 256>>>(src, dst);
    k_msg<<<dim3(N_NODES, 3), 256>>>(ef);
    k_gemm_mma<<<dim3(N_NODES / 128, BT), 128>>>(bvec, out);
}

// round 11
// speedup vs baseline: 1.2209x; 1.0077x over previous
#include <cuda_runtime.h>
#include <cstdint>

#define N_NODES 2048
#define N_EDGES 16384
#define B_DIM 8
#define C_DIM 64
#define T_DIM 12
#define BT 96                 // B*T
#define OUT_DIM 64

// ---------------- scratch (static __device__, no allocation) ----------------
__device__ float g_h2[N_NODES * BT * C_DIM];     // h * log2(e), [n][bt][c]
// feats pre-split to bf16 hi/lo, pre-SW128-swizzled per 128B row: [bt][n][128B]
__device__ __align__(16) uint8_t g_fh[BT * N_NODES * 128];
__device__ __align__(16) uint8_t g_fl[BT * N_NODES * 128];
// W^T pre-split bf16 hi/lo, pre-swizzled: [o][128B]
__device__ __align__(16) uint8_t g_wh[OUT_DIM * 128];
__device__ __align__(16) uint8_t g_wl[OUT_DIM * 128];
__device__ int   g_cnt[N_NODES];
__device__ int   g_epack[N_NODES * 64];          // (eid<<11)|src per dst slot

// ---------------- packed f32x2 helpers ----------------
union F2U { float2 f; unsigned long long u; };
__device__ __forceinline__ float2 f2add(float2 a, float2 b) {
    F2U A, B2, D; A.f = a; B2.f = b;
    asm("add.rn.f32x2 %0, %1, %2;" : "=l"(D.u) : "l"(A.u), "l"(B2.u));
    return D.f;
}
__device__ __forceinline__ float2 f2fma(float2 a, float2 b, float2 c) {
    F2U A, B2, C2, D; A.f = a; B2.f = b; C2.f = c;
    asm("fma.rn.f32x2 %0, %1, %2, %3;" : "=l"(D.u) : "l"(A.u), "l"(B2.u), "l"(C2.u));
    return D.f;
}
__device__ __forceinline__ float4 f4add(float4 a, float4 b) {
    float2 lo = f2add(make_float2(a.x, a.y), make_float2(b.x, b.y));
    float2 hi = f2add(make_float2(a.z, a.w), make_float2(b.z, b.w));
    return make_float4(lo.x, lo.y, hi.x, hi.y);
}
__device__ __forceinline__ float ex2f(float x) {
    float r; asm("ex2.approx.f32 %0, %1;" : "=f"(r) : "f"(x)); return r;
}
__device__ __forceinline__ float rcpf(float x) {
    float r; asm("rcp.approx.f32 %0, %1;" : "=f"(r) : "f"(x)); return r;
}
__device__ __forceinline__ uint32_t smem_u32(const void* p) {
    uint32_t a;
    asm("{ .reg .u64 t; cvta.to.shared.u64 t, %1; cvt.u32.u64 %0, t; }"
        : "=r"(a) : "l"(p));
    return a;
}
// split two fp32 into packed bf16x2 hi + lo (hi = rn(x), lo = rn(x - hi))
__device__ __forceinline__ void bf16_split2(float a, float b,
                                            uint32_t& hp, uint32_t& lp) {
    asm("cvt.rn.bf16x2.f32 %0, %1, %2;" : "=r"(hp) : "f"(b), "f"(a));
    float fa = __uint_as_float(hp << 16);
    float fb = __uint_as_float(hp & 0xffff0000u);
    float ra = a - fa, rb = b - fb;
    asm("cvt.rn.bf16x2.f32 %0, %1, %2;" : "=r"(lp) : "f"(rb), "f"(ra));
}
#define SW128(off) ((off) ^ (((off) >> 3) & 0x70))

// ---------------- stage A: transpose [B,C,T,N] -> [N,BT,C] (*log2e),
// extra z-slice: zero counters + prepare pre-swizzled bf16 hi/lo W^T ---------
__global__ void k_transpose(const float* __restrict__ nf,
                            const float* __restrict__ W) {
    if (blockIdx.z == BT) {
        if (blockIdx.x == 0 && blockIdx.y == 0) {
            int t = threadIdx.y * 32 + threadIdx.x;
            for (int i = t; i < N_NODES; i += 256) g_cnt[i] = 0;
            for (int i = t; i < 2048; i += 256) {   // i = o*32 + cp
                int o = i >> 5, cp = i & 31;
                float w0 = W[(2 * cp) * 64 + o];
                float w1 = W[(2 * cp + 1) * 64 + o];
                uint32_t hp, lp;
                bf16_split2(w0, w1, hp, lp);
                uint32_t off = SW128((uint32_t)(o * 128 + cp * 4));
                *(uint32_t*)(g_wh + off) = hp;
                *(uint32_t*)(g_wl + off) = lp;
            }
        }
        return;
    }
    __shared__ float tile[32][33];
    const float LOG2E = 1.4426950408889634f;
    int bt = blockIdx.z;
    int b = bt / T_DIM, t = bt - b * T_DIM;
    int c0 = blockIdx.y << 5, n0 = blockIdx.x << 5;
    int tx = threadIdx.x, ty = threadIdx.y;
#pragma unroll
    for (int i = 0; i < 4; i++) {
        int c = c0 + ty + i * 8;
        tile[ty + i * 8][tx] =
            nf[(((b * C_DIM + c) * T_DIM + t) * N_NODES) + n0 + tx] * LOG2E;
    }
    __syncthreads();
#pragma unroll
    for (int i = 0; i < 4; i++) {
        int n = n0 + ty + i * 8;
        g_h2[((n * BT + bt) << 6) + c0 + tx] = tile[tx][ty + i * 8];
    }
}

// ---------------- stage 0b: bucket-place edges per destination -------------
__global__ void k_build(const int* __restrict__ src, const int* __restrict__ dst) {
    int e = blockIdx.x * blockDim.x + threadIdx.x;
    int d = dst[e];
    int p = atomicAdd(&g_cnt[d], 1);
    g_epack[(d << 6) + p] = (e << 11) | src[e];
}

// ---------------- stage B: message + softmax + agg + residual ---------------
// grid (N_NODES, 6), block 256: cq = tid&15 (c-quad), grp = tid>>4 = bt slot.
// Each block covers 16 bt; each thread owns 1 bt x 4c -> 1 LDG.128 per edge.
// 4-edge unrolled mainloop gives MLP=4. Output bf16 hi/lo pre-swizzled.
#define BT_PER_BLK 16
__global__ __launch_bounds__(256) void k_msg(const float* __restrict__ ef) {
    __shared__ __align__(16) float s_ev[64 * 64];
    __shared__ int s_ep[64];
    __shared__ int s_cnt;
    int n = blockIdx.x;
    int tid = threadIdx.x;
    if (tid == 0) s_cnt = g_cnt[n];
    if (tid < 64) s_ep[tid] = g_epack[(n << 6) + tid];
    __syncthreads();
    int cnt = s_cnt;
    const float LOG2E = 1.4426950408889634f;
    for (int i = tid; i < (cnt << 6); i += 256) {
        int eid = s_ep[i >> 6] >> 11;
        s_ev[i] = ef[(eid << 6) + (i & 63)] * LOG2E;
    }
    __syncthreads();

    int cq = tid & 15;            // c-quad: c = 4*cq .. +3
    int grp = tid >> 4;           // bt slot 0..15
    int bt = blockIdx.y * BT_PER_BLK + grp;

    float4 den = make_float4(0, 0, 0, 0), num = den;
    const float4* evp = (const float4*)s_ev;

#define PROC(Hq, Eq)                                                       \
    {                                                                      \
        float4 v = f4add(Hq, Eq);                                          \
        float4 r = make_float4(fmaxf(v.x, 0.f), fmaxf(v.y, 0.f),           \
                               fmaxf(v.z, 0.f), fmaxf(v.w, 0.f));          \
        float4 p = make_float4(ex2f(r.x), ex2f(r.y), ex2f(r.z), ex2f(r.w)); \
        den = f4add(den, p);                                               \
        float2 nlo = f2fma(make_float2(r.x, r.y), make_float2(p.x, p.y),   \
                           make_float2(num.x, num.y));                     \
        float2 nhi = f2fma(make_float2(r.z, r.w), make_float2(p.z, p.w),   \
                           make_float2(num.z, num.w));                     \
        num = make_float4(nlo.x, nlo.y, nhi.x, nhi.y);                     \
    }

    int k = 0;
    for (; k + 4 <= cnt; k += 4) {
        int s0 = s_ep[k] & 2047;
        int s1 = s_ep[k + 1] & 2047;
        int s2 = s_ep[k + 2] & 2047;
        int s3 = s_ep[k + 3] & 2047;
        float4 a0 = *((const float4*)(g_h2 + (s0 * BT + bt) * 64) + cq);
        float4 a1 = *((const float4*)(g_h2 + (s1 * BT + bt) * 64) + cq);
        float4 a2 = *((const float4*)(g_h2 + (s2 * BT + bt) * 64) + cq);
        float4 a3 = *((const float4*)(g_h2 + (s3 * BT + bt) * 64) + cq);
        float4 e0 = evp[((k) << 4) + cq];
        float4 e1 = evp[((k + 1) << 4) + cq];
        float4 e2 = evp[((k + 2) << 4) + cq];
        float4 e3 = evp[((k + 3) << 4) + cq];
        PROC(a0, e0);
        PROC(a1, e1);
        PROC(a2, e2);
        PROC(a3, e3);
    }
    for (; k < cnt; k++) {
        int s0 = s_ep[k] & 2047;
        float4 a0 = *((const float4*)(g_h2 + (s0 * BT + bt) * 64) + cq);
        float4 e0 = evp[(k << 4) + cq];
        PROC(a0, e0);
    }
#undef PROC

    const float LN2 = 0.6931471805599453f;
    const float EPS = 1e-7f;
    float4 h = *((const float4*)(g_h2 + (n * BT + bt) * 64) + cq);
    float4 agg = make_float4(0, 0, 0, 0);
    if (cnt > 0) {
        agg.x = fmaf(num.x * rcpf(den.x), LN2, EPS);
        agg.y = fmaf(num.y * rcpf(den.y), LN2, EPS);
        agg.z = fmaf(num.z * rcpf(den.z), LN2, EPS);
        agg.w = fmaf(num.w * rcpf(den.w), LN2, EPS);
    }
    float4 o;
    o.x = fmaf(h.x, LN2, agg.x);
    o.y = fmaf(h.y, LN2, agg.y);
    o.z = fmaf(h.z, LN2, agg.z);
    o.w = fmaf(h.w, LN2, agg.w);
    // split to bf16 hi/lo, store pre-swizzled [bt][n][128B]
    uint32_t hx, lx, hy, ly;
    bf16_split2(o.x, o.y, hx, lx);
    bf16_split2(o.z, o.w, hy, ly);
    uint32_t chunk = ((uint32_t)(cq * 8)) ^ (((uint32_t)n & 7) << 4);
    size_t base = ((size_t)bt * N_NODES + n) * 128 + chunk;
    *(uint2*)(g_fh + base) = make_uint2(hx, hy);
    *(uint2*)(g_fl + base) = make_uint2(lx, ly);
}

// ---------------- stage C: HMMA bf16 GEMM (mma.sync), out [B,O,T,N] ---------
#define SM_AH 0
#define SM_AL 16384
#define SM_BH 32768
#define SM_BL 40960

__device__ __forceinline__ void ldsm4(uint32_t* r, uint32_t addr) {
    asm volatile("ldmatrix.sync.aligned.m8n8.x4.shared.b16 {%0,%1,%2,%3}, [%4];"
                 : "=r"(r[0]), "=r"(r[1]), "=r"(r[2]), "=r"(r[3]) : "r"(addr));
}
__device__ __forceinline__ void mma16816(float* d, const uint32_t* a,
                                         uint32_t b0, uint32_t b1) {
    asm volatile(
        "mma.sync.aligned.m16n8k16.row.col.f32.bf16.bf16.f32 "
        "{%0,%1,%2,%3}, {%4,%5,%6,%7}, {%8,%9}, {%0,%1,%2,%3};"
        : "+f"(d[0]), "+f"(d[1]), "+f"(d[2]), "+f"(d[3])
        : "r"(a[0]), "r"(a[1]), "r"(a[2]), "r"(a[3]), "r"(b0), "r"(b1));
}

__global__ __launch_bounds__(128) void k_gemm_mma(const float* __restrict__ bias,
                                                  float* __restrict__ out) {
    __shared__ __align__(1024) uint8_t smem[49152];
    uint32_t sb = smem_u32(smem);
    int tid = threadIdx.x;
    int bt = blockIdx.y;
    int n0 = blockIdx.x << 7;

    // ---- prologue: pure coalesced copies (pre-swizzled in gmem) ----
    {
        const uint4* sH = (const uint4*)(g_fh + ((size_t)bt * N_NODES + n0) * 128);
        const uint4* sL = (const uint4*)(g_fl + ((size_t)bt * N_NODES + n0) * 128);
        uint4* dH = (uint4*)(smem + SM_AH);
        uint4* dL = (uint4*)(smem + SM_AL);
#pragma unroll
        for (int i = 0; i < 8; i++) {
            dH[tid + i * 128] = sH[tid + i * 128];
            dL[tid + i * 128] = sL[tid + i * 128];
        }
        const uint4* wH = (const uint4*)g_wh;
        const uint4* wL = (const uint4*)g_wl;
        uint4* bH = (uint4*)(smem + SM_BH);
        uint4* bL = (uint4*)(smem + SM_BL);
#pragma unroll
        for (int i = 0; i < 4; i++) {
            bH[tid + i * 128] = wH[tid + i * 128];
            bL[tid + i * 128] = wL[tid + i * 128];
        }
    }
    __syncthreads();

    int w = tid >> 5, lane = tid & 31;
    int lr = (lane & 7) + ((lane >> 3) & 1) * 8;
    int lc = (lane >> 4) * 16;

    float acc[2][8][4];
#pragma unroll
    for (int mi = 0; mi < 2; mi++)
#pragma unroll
        for (int ni = 0; ni < 8; ni++)
#pragma unroll
            for (int q = 0; q < 4; q++) acc[mi][ni][q] = 0.f;

    const uint32_t aoff[3] = {SM_AH, SM_AL, SM_AH};
    const uint32_t boff[3] = {SM_BH, SM_BH, SM_BL};

#pragma unroll
    for (int pass = 0; pass < 3; pass++) {
        uint32_t Ab = sb + aoff[pass];
        uint32_t Bb = sb + boff[pass];
#pragma unroll
        for (int k = 0; k < 4; k++) {
            int cb = k * 32 + lc;
            uint32_t a[2][4];
#pragma unroll
            for (int mi = 0; mi < 2; mi++) {
                uint32_t row = w * 32 + mi * 16 + lr;
                ldsm4(a[mi], Ab + SW128(row * 128 + cb));
            }
            uint32_t b[4][4];
#pragma unroll
            for (int p = 0; p < 4; p++) {
                uint32_t row = p * 16 + lr;
                ldsm4(b[p], Bb + SW128(row * 128 + cb));
            }
#pragma unroll
            for (int mi = 0; mi < 2; mi++)
#pragma unroll
                for (int ni = 0; ni < 8; ni++)
                    mma16816(acc[mi][ni], a[mi],
                             b[ni >> 1][ni & 1], b[ni >> 1][2 + (ni & 1)]);
        }
    }

    // ---- epilogue: smem staging (pitch 132, conflict-free) -> STG.128 ----
    __syncthreads();
    float* so = (float*)smem;
    int g = lane >> 2, t4 = lane & 3;
#pragma unroll
    for (int mi = 0; mi < 2; mi++) {
        int n_lo = w * 32 + mi * 16 + g;
#pragma unroll
        for (int ni = 0; ni < 8; ni++) {
            int o0 = (ni << 3) + (t4 << 1);
            so[o0 * 132 + n_lo] = acc[mi][ni][0];
            so[(o0 + 1) * 132 + n_lo] = acc[mi][ni][1];
            so[o0 * 132 + n_lo + 8] = acc[mi][ni][2];
            so[(o0 + 1) * 132 + n_lo + 8] = acc[mi][ni][3];
        }
    }
    __syncthreads();

    int b = bt / T_DIM, tt = bt - b * T_DIM;
    const long long OSTRIDE = (long long)T_DIM * N_NODES;
    float* ob = out + ((long long)(b * OUT_DIM) * T_DIM + tt) * N_NODES + n0;
#pragma unroll
    for (int it = 0; it < 16; it++) {
        int idx = it * 128 + tid;
        int o = idx >> 5, q4 = idx & 31;
        float4 v = *(const float4*)&so[o * 132 + (q4 << 2)];
        float bb = __ldg(bias + o);
        v.x += bb; v.y += bb; v.z += bb; v.w += bb;
        *(float4*)(ob + (long long)o * OSTRIDE + (q4 << 2)) = v;
    }
}

// ---------------- launch ----------------
extern "C" void kernel_launch(void* const* d_in, const int* in_sizes, int n_in,
                              void* d_out, int out_size) {
    const float* nf   = (const float*)d_in[0];  // node_feats [B,C,T,N]
    const float* ef   = (const float*)d_in[1];  // edge_feat  [E,1,1,C]
    const int*   src  = (const int*)d_in[2];
    const int*   dst  = (const int*)d_in[3];
    const float* W    = (const float*)d_in[4];
    const float* bvec = (const float*)d_in[5];
    float* out = (float*)d_out;

    k_transpose<<<dim3(N_NODES / 32, C_DIM / 32, BT + 1), dim3(32, 8)>>>(nf, W);
    k_build<<<N_EDGES / 256, 256>>>(src, dst);
    k_msg<<<dim3(N_NODES, BT / BT_PER_BLK), 256>>>(ef);
    k_gemm_mma<<<dim3(N_NODES / 128, BT), 128>>>(bvec, out);
}